// round 16
// baseline (speedup 1.0000x reference)
#include <cuda_runtime.h>
#include <math.h>

// Problem constants
#define Bc 32
#define Nc 256
#define Tc 64
#define Mc 64
#define Hc 512
#define Wc 512
#define COL_THRESH 0.5f

#define THREADS 64                  // one candidate per 64-thread block
#define BLKS_PER_B Nc               // 256 blocks per batch -> 8192 blocks

// Scratch for raw per-(b,n) scores: [f_dis, f_pg, min_col_sq, f_dac]
__device__ float4 g_scratch[Bc * Nc];
// Per-batch completion counters (zero-initialized; reset by the winner)
__device__ int g_cnt[Bc];

// ---------------------------------------------------------------------------
// Fused kernel. grid = (256, B), block = 64 threads (R2's winning geometry).
// Phase 1: one candidate per block, one thread per timestep.
// Phase 2: the LAST block per batch (threadfence-reduction) normalizes,
//          argmaxes and copies the best trajectory with 64 threads
//          handling 4 candidates each.
// ---------------------------------------------------------------------------
__global__ __launch_bounds__(THREADS) void fused_kernel(
    const float* __restrict__ traj,     // (B,N,T,2)
    const float* __restrict__ goal,     // (B,2)
    const float* __restrict__ gt,       // (B,T,2)
    const float* __restrict__ obs,      // (B,M,2)
    const float* __restrict__ da,       // (B,H,W)
    float* __restrict__ out)            // [B*T*2 best | B*N scores]
{
    const int n   = blockIdx.x;          // candidate
    const int b   = blockIdx.y;          // batch
    const int t   = threadIdx.x;         // timestep 0..63
    const int lane = t & 31, w = t >> 5; // warp-in-block: 0/1

    __shared__ float4 s_obs[Mc];   // (-2*ox, -2*oy, |o|^2, pad)
    __shared__ float  s_red[3][2];
    __shared__ float  s_pg;
    __shared__ int    s_last;

    // ===== front-batched loads =====
    // my trajectory point (coalesced float2)
    const float2 p = ((const float2*)traj)[((size_t)(b * Nc + n)) * Tc + t];

    // gt point
    const float2 g = __ldg(&((const float2*)gt)[b * Tc + t]);

    // goal (endpoint thread only)
    float2 gl = make_float2(0.0f, 0.0f);
    if (t == Tc - 1) gl = ((const float2*)goal)[b];

    // obstacle prefetch (one per thread)
    const float2 opre = ((const float2*)obs)[b * Mc + t];

    // DAC gather issued early; consumed after the collision loop
    int xi = (int)((p.x + 50.0f) / 100.0f * (float)(Wc - 1));
    int yi = (int)((p.y + 50.0f) / 100.0f * (float)(Hc - 1));
    xi = min(max(xi, 0), Wc - 1);
    yi = min(max(yi, 0), Hc - 1);
    const float dval = __ldg(&da[(size_t)b * (Hc * Wc) + yi * Wc + xi]);

    // stage transformed obstacle
    {
        float o2 = fmaf(opre.x, opre.x, opre.y * opre.y);
        s_obs[t] = make_float4(-2.0f * opre.x, -2.0f * opre.y, o2, 0.0f);
    }

    // --- distance-to-GT while the STS drains ---
    float dxg = p.x - g.x, dyg = p.y - g.y;
    float dis = sqrtf(fmaf(dxg, dxg, dyg * dyg));

    // --- progress term ---
    if (t == Tc - 1) {
        float ex = p.x - gl.x, ey = p.y - gl.y;
        s_pg = sqrtf(fmaf(ex, ex, ey * ey));
    }

    __syncthreads();   // obstacles visible

    // --- collision: min over M of (|o|^2 - 2 p.o); 4 independent chains ---
    const float BIG = 3.402823466e+38f;
    float m0 = BIG, m1 = BIG, m2 = BIG, m3 = BIG;
#pragma unroll
    for (int m = 0; m < Mc; m += 4) {
        float4 o0 = s_obs[m + 0];
        float4 o1 = s_obs[m + 1];
        float4 o2 = s_obs[m + 2];
        float4 o3 = s_obs[m + 3];
        m0 = fminf(m0, fmaf(p.y, o0.y, fmaf(p.x, o0.x, o0.z)));
        m1 = fminf(m1, fmaf(p.y, o1.y, fmaf(p.x, o1.x, o1.z)));
        m2 = fminf(m2, fmaf(p.y, o2.y, fmaf(p.x, o2.x, o2.z)));
        m3 = fminf(m3, fmaf(p.y, o3.y, fmaf(p.x, o3.x, o3.z)));
    }
    float p2 = fmaf(p.x, p.x, p.y * p.y);
    float mind2 = p2 + fminf(fminf(m0, m1), fminf(m2, m3));
    mind2 = fmaxf(mind2, 0.0f);   // guard cancellation before sqrt later

    // --- consume DAC gather ---
    float dac = 1.0f - dval;

    // --- reduction over 64 threads: warp shuffle + 2-warp combine ---
#pragma unroll
    for (int off = 16; off > 0; off >>= 1) {
        dis   += __shfl_xor_sync(0xFFFFFFFFu, dis, off);
        dac   += __shfl_xor_sync(0xFFFFFFFFu, dac, off);
        mind2  = fminf(mind2, __shfl_xor_sync(0xFFFFFFFFu, mind2, off));
    }
    if (lane == 0) {
        s_red[0][w] = dis;
        s_red[1][w] = mind2;
        s_red[2][w] = dac;
    }
    __syncthreads();

    if (t == 0) {
        float f_dis  = (s_red[0][0] + s_red[0][1]) * (1.0f / Tc);
        float mcolsq = fminf(s_red[1][0], s_red[1][1]);
        float f_dac  = (s_red[2][0] + s_red[2][1]) * (1.0f / Tc);
        g_scratch[b * Nc + n] = make_float4(f_dis, s_pg, mcolsq, f_dac);
        __threadfence();            // storer releases its own write
        int old = atomicAdd(&g_cnt[b], 1);
        s_last = (old == BLKS_PER_B - 1) ? 1 : 0;
    }
    __syncthreads();
    if (!s_last) return;
    __threadfence();                // acquire all blocks' scratch writes

    // =======================================================================
    // Phase 2 (one 64-thread block per batch): 4 candidates per thread.
    // =======================================================================
    {
        __shared__ float s_mn2[2][4], s_mx2[2][4];
        __shared__ float s_bs2[2];
        __shared__ int   s_bi2[2];

        // load 4 candidates' raw scores (nn = k*64 + t)
        float v[4][4];
#pragma unroll
        for (int k = 0; k < 4; k++) {
            const float4* sc = &g_scratch[b * Nc + (k * 64 + t)];
            float4 raw;
            raw.x = __ldcg(&sc->x);
            raw.y = __ldcg(&sc->y);
            raw.z = __ldcg(&sc->z);
            raw.w = __ldcg(&sc->w);
            float ttv = sqrtf(raw.z) - COL_THRESH;
            v[k][0] = raw.x;
            v[k][1] = raw.y;
            v[k][2] = expf(-(ttv * ttv));
            v[k][3] = raw.w;
        }

        // local + warp min/max
        float mn4[4], mx4[4];
#pragma unroll
        for (int i = 0; i < 4; i++) {
            mn4[i] = fminf(fminf(v[0][i], v[1][i]), fminf(v[2][i], v[3][i]));
            mx4[i] = fmaxf(fmaxf(v[0][i], v[1][i]), fmaxf(v[2][i], v[3][i]));
        }
#pragma unroll
        for (int off = 16; off > 0; off >>= 1) {
#pragma unroll
            for (int i = 0; i < 4; i++) {
                mn4[i] = fminf(mn4[i], __shfl_xor_sync(0xFFFFFFFFu, mn4[i], off));
                mx4[i] = fmaxf(mx4[i], __shfl_xor_sync(0xFFFFFFFFu, mx4[i], off));
            }
        }
        if (lane == 0) {
#pragma unroll
            for (int i = 0; i < 4; i++) { s_mn2[w][i] = mn4[i]; s_mx2[w][i] = mx4[i]; }
        }
        __syncthreads();

        // every thread combines the two warps' results (no extra barrier)
        float fmn[4], fmx[4];
#pragma unroll
        for (int i = 0; i < 4; i++) {
            fmn[i] = fminf(s_mn2[0][i], s_mn2[1][i]);
            fmx[i] = fmaxf(s_mx2[0][i], s_mx2[1][i]);
        }

        // scores + output
        float* out_scores = out + (Bc * Tc * 2);
        float sc4[4];
#pragma unroll
        for (int k = 0; k < 4; k++) {
            float s = 0.0f;
#pragma unroll
            for (int i = 0; i < 4; i++) {
                float d = fmx[i] - fmn[i];
                d = (d == 0.0f) ? 1.0f : d;
                s += (v[k][i] - fmn[i]) / d;
            }
            sc4[k] = -s;
            out_scores[b * Nc + (k * 64 + t)] = sc4[k];
        }

        // argmax with first-index tie-break (local k ascending => strict >)
        float bs = sc4[0];
        int   bi = t;
#pragma unroll
        for (int k = 1; k < 4; k++) {
            if (sc4[k] > bs) { bs = sc4[k]; bi = k * 64 + t; }
        }
#pragma unroll
        for (int off = 16; off > 0; off >>= 1) {
            float os = __shfl_xor_sync(0xFFFFFFFFu, bs, off);
            int   oi = __shfl_xor_sync(0xFFFFFFFFu, bi, off);
            if (os > bs || (os == bs && oi < bi)) { bs = os; bi = oi; }
        }
        if (lane == 0) { s_bs2[w] = bs; s_bi2[w] = bi; }
        __syncthreads();

        // every thread combines the two warps (no extra barrier)
        int best;
        {
            float b0 = s_bs2[0], b1 = s_bs2[1];
            int   i0 = s_bi2[0], i1 = s_bi2[1];
            best = (b1 > b0 || (b1 == b0 && i1 < i0)) ? i1 : i0;
        }

        // copy best trajectory: 64 float2, one per thread
        ((float2*)out)[b * Tc + t] =
            ((const float2*)traj)[((size_t)(b * Nc + best)) * Tc + t];

        // reset counter for the next graph replay (all arrivals already in)
        if (t == 0) g_cnt[b] = 0;
    }
}

// ---------------------------------------------------------------------------
// Launch
// ---------------------------------------------------------------------------
extern "C" void kernel_launch(void* const* d_in, const int* in_sizes, int n_in,
                              void* d_out, int out_size)
{
    const float* traj = (const float*)d_in[0];   // (B,N,T,2)
    const float* goal = (const float*)d_in[1];   // (B,2)
    const float* gt   = (const float*)d_in[2];   // (B,T,2)
    const float* obs  = (const float*)d_in[3];   // (B,M,2)
    const float* da   = (const float*)d_in[4];   // (B,H,W)
    float* out = (float*)d_out;

    dim3 g1(BLKS_PER_B, Bc);
    fused_kernel<<<g1, THREADS>>>(traj, goal, gt, obs, da, out);
}

// round 17
// speedup vs baseline: 1.2693x; 1.2693x over previous
#include <cuda_runtime.h>
#include <math.h>

// Problem constants
#define Bc 32
#define Nc 256
#define Tc 64
#define Mc 64
#define Hc 512
#define Wc 512
#define COL_THRESH 0.5f

#define GRP 8                       // threads per candidate (per half)
#define T_PER_THR 8                 // timesteps per thread
#define CAND_PER_BLK 16             // candidates per block
#define THREADS 256                 // two 128-thread halves (obstacle split)
#define BLKS_PER_B (Nc / CAND_PER_BLK)   // 16 blocks per batch -> 512 blocks

// Scratch for raw per-(b,n) scores: [f_dis, f_pg, min_col_sq, f_dac]
__device__ float4 g_scratch[Bc * Nc];
// Per-batch completion counters (zero-initialized; reset by the winner)
__device__ int g_cnt[Bc];

// ---------------------------------------------------------------------------
// Fused kernel. grid = (16, B), block = 256 — 512 blocks, 4096 warps (~43% occ)
// with R13's LDS/DAC traffic (obstacle loop split across block halves).
// half 0: points + dis/pg/DAC + obstacles [0,32)
// half 1: same points (L1-hit reloads) + obstacles [32,64) only
// Phase 2: LAST block per batch normalizes, argmaxes, copies best trajectory.
// ---------------------------------------------------------------------------
__global__ __launch_bounds__(THREADS) void fused_kernel(
    const float* __restrict__ traj,     // (B,N,T,2)
    const float* __restrict__ goal,     // (B,2)
    const float* __restrict__ gt,       // (B,T,2)
    const float* __restrict__ obs,      // (B,M,2)
    const float* __restrict__ da,       // (B,H,W)
    float* __restrict__ out)            // [B*T*2 best | B*N scores]
{
    const int b    = blockIdx.y;
    const int tid  = threadIdx.x;
    const int half = tid >> 7;                      // 0 or 1 (warp-aligned)
    const int hid  = tid & 127;
    const int c    = hid >> 3;                      // candidate slot 0..15
    const int tg   = hid & 7;                       // thread-in-group 0..7
    const int n    = blockIdx.x * CAND_PER_BLK + c; // candidate index
    const int t0   = tg * T_PER_THR;                // first timestep

    __shared__ float4 s_obs[Mc];   // (-2*ox, -2*oy, |o|^2, pad)
    __shared__ float  s_m2[CAND_PER_BLK];   // half-1 collision partials
    __shared__ int    s_last;

    // ===== front-batched loads =====
    // my 8 trajectory points (half 1 re-loads the same lines -> L1 hits)
    const float4* traj4 = (const float4*)traj;
    const int base4 = ((b * Nc + n) * Tc + t0) >> 1;
    float4 q0 = traj4[base4];
    float4 q1 = traj4[base4 + 1];
    float4 q2 = traj4[base4 + 2];
    float4 q3 = traj4[base4 + 3];

    // obstacle prefetch into registers (first 64 threads)
    float2 opre = make_float2(0.0f, 0.0f);
    if (tid < Mc) opre = ((const float2*)obs)[b * Mc + tid];

    float px[8] = {q0.x, q0.z, q1.x, q1.z, q2.x, q2.z, q3.x, q3.z};
    float py[8] = {q0.y, q0.w, q1.y, q1.w, q2.y, q2.w, q3.y, q3.w};

    float dis = 0.0f, pg = 0.0f, dac = 0.0f;
    float dval[8];

    if (half == 0) {
        // DAC gathers issued early so latency hides under the loop
#pragma unroll
        for (int j = 0; j < 8; j++) {
            int xi = (int)((px[j] + 50.0f) / 100.0f * (float)(Wc - 1));
            int yi = (int)((py[j] + 50.0f) / 100.0f * (float)(Hc - 1));
            xi = min(max(xi, 0), Wc - 1);
            yi = min(max(yi, 0), Hc - 1);
            dval[j] = __ldg(&da[(size_t)b * (Hc * Wc) + yi * Wc + xi]);
        }
    }

    // stage transformed obstacles into shared
    if (tid < Mc) {
        float o2 = fmaf(opre.x, opre.x, opre.y * opre.y);
        s_obs[tid] = make_float4(-2.0f * opre.x, -2.0f * opre.y, o2, 0.0f);
    }

    if (half == 0) {
        // distance-to-GT while the STS drains
        const float4* gt4 = (const float4*)gt;
        const int gbase4 = (b * Tc + t0) >> 1;
        float4 G0 = __ldg(&gt4[gbase4]);
        float4 G1 = __ldg(&gt4[gbase4 + 1]);
        float4 G2 = __ldg(&gt4[gbase4 + 2]);
        float4 G3 = __ldg(&gt4[gbase4 + 3]);
        float gx[8] = {G0.x, G0.z, G1.x, G1.z, G2.x, G2.z, G3.x, G3.z};
        float gy[8] = {G0.y, G0.w, G1.y, G1.w, G2.y, G2.w, G3.y, G3.w};
#pragma unroll
        for (int j = 0; j < 8; j++) {
            float dx = px[j] - gx[j], dy = py[j] - gy[j];
            dis += sqrtf(fmaf(dx, dx, dy * dy));
        }
        // progress term (endpoint owner)
        if (tg == GRP - 1) {
            float2 gl = ((const float2*)goal)[b];
            float ex = px[7] - gl.x, ey = py[7] - gl.y;
            pg = sqrtf(fmaf(ex, ex, ey * ey));
        }
    }

    __syncthreads();   // obstacles visible

    // --- collision: this half's 32 obstacles; min of (|o|^2 - 2 p.o)/pt ---
    const float BIG = 3.402823466e+38f;
    float mc[8] = {BIG, BIG, BIG, BIG, BIG, BIG, BIG, BIG};
    const int mbase = half << 5;   // 0 or 32
#pragma unroll 4
    for (int m = 0; m < 32; m++) {
        float4 o = s_obs[mbase + m];   // broadcast, conflict-free
#pragma unroll
        for (int j = 0; j < 8; j++)
            mc[j] = fminf(mc[j], fmaf(py[j], o.y, fmaf(px[j], o.x, o.z)));
    }
    float mind2 = BIG;
#pragma unroll
    for (int j = 0; j < 8; j++)
        mind2 = fminf(mind2, fmaf(px[j], px[j], py[j] * py[j]) + mc[j]);
    mind2 = fmaxf(mind2, 0.0f);    // clamp commutes with min across halves

    if (half == 0) {
        // consume DAC gathers
#pragma unroll
        for (int j = 0; j < 8; j++) dac += 1.0f - dval[j];
        // 8-lane group reduction (all four quantities)
#pragma unroll
        for (int off = 4; off > 0; off >>= 1) {
            dis   += __shfl_xor_sync(0xFFFFFFFFu, dis, off);
            dac   += __shfl_xor_sync(0xFFFFFFFFu, dac, off);
            pg    += __shfl_xor_sync(0xFFFFFFFFu, pg, off);
            mind2  = fminf(mind2, __shfl_xor_sync(0xFFFFFFFFu, mind2, off));
        }
    } else {
        // 8-lane group reduction (collision only), publish partial
#pragma unroll
        for (int off = 4; off > 0; off >>= 1)
            mind2 = fminf(mind2, __shfl_xor_sync(0xFFFFFFFFu, mind2, off));
        if (tg == 0) s_m2[c] = mind2;
    }
    __syncthreads();   // half-1 partials visible

    if (half == 0 && tg == 0) {
        float mfull = fminf(mind2, s_m2[c]);
        g_scratch[b * Nc + n] =
            make_float4(dis * (1.0f / Tc), pg, mfull, dac * (1.0f / Tc));
        __threadfence();   // storer releases its own write
    }
    __syncthreads();

    // ---- completion signalling: last block for this batch does the select ---
    if (tid == 0) {
        int old = atomicAdd(&g_cnt[b], 1);
        s_last = (old == BLKS_PER_B - 1) ? 1 : 0;
    }
    __syncthreads();
    if (!s_last) return;
    __threadfence();                          // acquire others' scratch writes

    // =======================================================================
    // Phase 2 (one block per batch): 256 threads, 1 candidate per thread.
    // =======================================================================
    {
        const int nn    = tid;
        const int lane2 = tid & 31;
        const int w2    = tid >> 5;   // 0..7

        __shared__ float s_mn[8][4], s_mx[8][4];
        __shared__ float s_fmn[4], s_fmx[4];
        __shared__ float s_bs[8];
        __shared__ int   s_bi[8];
        __shared__ int   s_best;

        // L2-coherent vector read of this candidate's raw scores
        float4 raw = __ldcg(&g_scratch[b * Nc + nn]);

        float mcol = sqrtf(raw.z);
        float ttv  = mcol - COL_THRESH;
        float v[4];
        v[0] = raw.x;               // f_dis
        v[1] = raw.y;               // f_pg
        v[2] = expf(-(ttv * ttv));  // f_col
        v[3] = raw.w;               // f_dac

        // --- combined 8-value reduction (4 mins + 4 maxes) ---
        float mn4[4], mx4[4];
#pragma unroll
        for (int i = 0; i < 4; i++) { mn4[i] = v[i]; mx4[i] = v[i]; }
#pragma unroll
        for (int off = 16; off > 0; off >>= 1) {
#pragma unroll
            for (int i = 0; i < 4; i++) {
                mn4[i] = fminf(mn4[i], __shfl_xor_sync(0xFFFFFFFFu, mn4[i], off));
                mx4[i] = fmaxf(mx4[i], __shfl_xor_sync(0xFFFFFFFFu, mx4[i], off));
            }
        }
        if (lane2 == 0) {
#pragma unroll
            for (int i = 0; i < 4; i++) { s_mn[w2][i] = mn4[i]; s_mx[w2][i] = mx4[i]; }
        }
        __syncthreads();
        if (w2 == 0) {   // full warp participates — convergent shuffles
#pragma unroll
            for (int i = 0; i < 4; i++) {
                mn4[i] = s_mn[lane2 & 7][i];
                mx4[i] = s_mx[lane2 & 7][i];
            }
#pragma unroll
            for (int off = 4; off > 0; off >>= 1) {
#pragma unroll
                for (int i = 0; i < 4; i++) {
                    mn4[i] = fminf(mn4[i], __shfl_xor_sync(0xFFFFFFFFu, mn4[i], off));
                    mx4[i] = fmaxf(mx4[i], __shfl_xor_sync(0xFFFFFFFFu, mx4[i], off));
                }
            }
            if (lane2 == 0) {
#pragma unroll
                for (int i = 0; i < 4; i++) { s_fmn[i] = mn4[i]; s_fmx[i] = mx4[i]; }
            }
        }
        __syncthreads();

        float score = 0.0f;
#pragma unroll
        for (int i = 0; i < 4; i++) {
            float d = s_fmx[i] - s_fmn[i];
            d = (d == 0.0f) ? 1.0f : d;
            score += (v[i] - s_fmn[i]) / d;
        }
        score = -score;

        // scores output region follows the best_trajectory block
        float* out_scores = out + (Bc * Tc * 2);
        out_scores[b * Nc + nn] = score;

        // --- argmax with first-index tie-break (matches jnp.argmax) ---
        float bs = score;
        int   bi = nn;
#pragma unroll
        for (int off = 16; off > 0; off >>= 1) {
            float os = __shfl_xor_sync(0xFFFFFFFFu, bs, off);
            int   oi = __shfl_xor_sync(0xFFFFFFFFu, bi, off);
            if (os > bs || (os == bs && oi < bi)) { bs = os; bi = oi; }
        }
        if (lane2 == 0) { s_bs[w2] = bs; s_bi[w2] = bi; }
        __syncthreads();
        if (w2 == 0) {   // full warp participates — convergent shuffles
            bs = s_bs[lane2 & 7];
            bi = s_bi[lane2 & 7];
#pragma unroll
            for (int off = 4; off > 0; off >>= 1) {
                float os = __shfl_xor_sync(0xFFFFFFFFu, bs, off);
                int   oi = __shfl_xor_sync(0xFFFFFFFFu, bi, off);
                if (os > bs || (os == bs && oi < bi)) { bs = os; bi = oi; }
            }
            if (lane2 == 0) s_best = bi;
        }
        __syncthreads();

        // --- copy best trajectory: T*2 = 128 floats = 64 float2 ---
        const int best = s_best;
        if (tid < Tc) {
            ((float2*)out)[b * Tc + tid] =
                ((const float2*)traj)[((size_t)(b * Nc + best)) * Tc + tid];
        }

        // reset counter for the next graph replay (all arrivals already in)
        if (tid == 0) g_cnt[b] = 0;
    }
}

// ---------------------------------------------------------------------------
// Launch
// ---------------------------------------------------------------------------
extern "C" void kernel_launch(void* const* d_in, const int* in_sizes, int n_in,
                              void* d_out, int out_size)
{
    const float* traj = (const float*)d_in[0];   // (B,N,T,2)
    const float* goal = (const float*)d_in[1];   // (B,2)
    const float* gt   = (const float*)d_in[2];   // (B,T,2)
    const float* obs  = (const float*)d_in[3];   // (B,M,2)
    const float* da   = (const float*)d_in[4];   // (B,H,W)
    float* out = (float*)d_out;

    dim3 g1(BLKS_PER_B, Bc);
    fused_kernel<<<g1, THREADS>>>(traj, goal, gt, obs, da, out);
}